// round 1
// baseline (speedup 1.0000x reference)
#include <cuda_runtime.h>
#include <cuda_bf16.h>

#define N_NODES 50000
#define N_EDGES 800000
#define IN_DIM  128
#define OUT_DIM 256

// Scratch (device globals: no allocation allowed in kernel_launch)
__device__ float g_msg[N_NODES * IN_DIM];   // neighbor feature sums
__device__ float g_deg[N_NODES];            // in-degree (as float)
__device__ int   g_is64;                    // 1 if src/dst are int64, 0 if int32

// ---------------------------------------------------------------------------
// Detect whether the index buffers are int64 or int32.
// If int64: values < 50000 -> every odd 32-bit word is exactly 0.
// If int32: odd words are uniform in [0, 50000) -> P(all 64 samples zero) ~ 0.
// ---------------------------------------------------------------------------
__global__ void detect_kernel(const int* __restrict__ idx) {
    int l = threadIdx.x;                      // 32 threads
    int v0 = idx[2 * l + 1];
    int v1 = idx[2 * (l + 32) + 1];
    unsigned ok = __ballot_sync(0xFFFFFFFFu, (v0 == 0) && (v1 == 0));
    if (l == 0) g_is64 = (ok == 0xFFFFFFFFu) ? 1 : 0;
}

// ---------------------------------------------------------------------------
// Zero the scratch accumulators (must run every replay).
// ---------------------------------------------------------------------------
__global__ void zero_kernel() {
    int tid    = blockIdx.x * blockDim.x + threadIdx.x;
    int stride = gridDim.x * blockDim.x;
    float4* m4 = (float4*)g_msg;
    int total4 = (N_NODES * IN_DIM) / 4;
    float4 z = make_float4(0.f, 0.f, 0.f, 0.f);
    for (int i = tid; i < total4; i += stride) m4[i] = z;
    for (int i = tid; i < N_NODES; i += stride) g_deg[i] = 0.f;
}

// ---------------------------------------------------------------------------
// Edge scatter: one warp per edge. Lane l owns float4 l of the 128-dim row.
// feat[src] gather is L2-resident (25.6MB). Reduction via red.global.add.v4.f32
// (sm_90+ vector reduction, no return value -> REDG path).
// ---------------------------------------------------------------------------
__global__ void scatter_kernel(const float4* __restrict__ feat4,
                               const void* __restrict__ srcp,
                               const void* __restrict__ dstp) {
    int lane   = threadIdx.x & 31;
    int warp   = (blockIdx.x * blockDim.x + threadIdx.x) >> 5;
    int nwarps = (gridDim.x * blockDim.x) >> 5;
    int is64   = g_is64;
    const long long* s64 = (const long long*)srcp;
    const long long* d64 = (const long long*)dstp;
    const int*       s32 = (const int*)srcp;
    const int*       d32 = (const int*)dstp;

    for (int e = warp; e < N_EDGES; e += nwarps) {
        int s, d;
        if (is64) { s = (int)s64[e]; d = (int)d64[e]; }
        else      { s = s32[e];      d = d32[e];      }
        float4 v = feat4[s * (IN_DIM / 4) + lane];
        float* p = &g_msg[d * IN_DIM + lane * 4];
        asm volatile("red.global.add.v4.f32 [%0], {%1,%2,%3,%4};"
                     :: "l"(p), "f"(v.x), "f"(v.y), "f"(v.z), "f"(v.w)
                     : "memory");
        if (lane == 0) atomicAdd(&g_deg[d], 1.0f);
    }
}

// ---------------------------------------------------------------------------
// Fused epilogue GEMM:  out = relu( (feat*0.5 + msg*(0.5/max(deg,1))) @ W )
// CTA tile: 64 rows x 256 cols (full OUT_DIM). 256 threads.
// Thread micro-tile: 8x8.  A tile in smem (broadcast reads per warp),
// W streamed in K-chunks of 32 through smem.
// ---------------------------------------------------------------------------
#define TM 64
#define KCHUNK 32
#define GEMM_SMEM ((TM * IN_DIM + KCHUNK * OUT_DIM) * 4)   // 64 KB

extern __shared__ float sm_dyn[];

__global__ __launch_bounds__(256) void fused_gemm(const float* __restrict__ feat,
                                                  const float* __restrict__ W,
                                                  float* __restrict__ out) {
    float* As = sm_dyn;                    // [TM][IN_DIM]
    float* Bs = sm_dyn + TM * IN_DIM;      // [KCHUNK][OUT_DIM]
    int t     = threadIdx.x;
    int mbase = blockIdx.x * TM;

    // ---- Load + compute A tile: x = feat*0.5 + msg*(0.5/max(deg,1)) ----
    // 64 rows x 32 float4 = 2048 float4; 8 per thread.
    #pragma unroll
    for (int i = 0; i < 8; i++) {
        int f   = t + i * 256;          // float4 index in tile
        int m   = f >> 5;               // row within tile
        int kq  = f & 31;               // float4 column
        int row = mbase + m;
        float4 a = make_float4(0.f, 0.f, 0.f, 0.f);
        if (row < N_NODES) {
            float4 fv = ((const float4*)feat)[row * 32 + kq];
            float4 mv = ((const float4*)g_msg)[row * 32 + kq];
            float inv = 0.5f / fmaxf(g_deg[row], 1.0f);
            a.x = fv.x * 0.5f + mv.x * inv;
            a.y = fv.y * 0.5f + mv.y * inv;
            a.z = fv.z * 0.5f + mv.z * inv;
            a.w = fv.w * 0.5f + mv.w * inv;
        }
        As[m * IN_DIM + kq * 4 + 0] = a.x;
        As[m * IN_DIM + kq * 4 + 1] = a.y;
        As[m * IN_DIM + kq * 4 + 2] = a.z;
        As[m * IN_DIM + kq * 4 + 3] = a.w;
    }

    float acc[8][8];
    #pragma unroll
    for (int i = 0; i < 8; i++)
        #pragma unroll
        for (int j = 0; j < 8; j++) acc[i][j] = 0.f;

    int tn = t & 31;    // column group: cols tn*8 .. tn*8+7
    int tw = t >> 5;    // warp id: rows tw*8 .. tw*8+7

    for (int kk = 0; kk < IN_DIM; kk += KCHUNK) {
        __syncthreads();   // A-tile ready (first iter) / Bs reads done (later)
        // ---- Load W chunk [KCHUNK][OUT_DIM]: 2048 float4, 8 per thread ----
        #pragma unroll
        for (int i = 0; i < 8; i++) {
            int f  = t + i * 256;
            int kr = f >> 6;            // row within chunk (64 float4 per row)
            int nq = f & 63;
            ((float4*)Bs)[kr * 64 + nq] =
                ((const float4*)W)[(kk + kr) * 64 + nq];
        }
        __syncthreads();

        #pragma unroll
        for (int kr = 0; kr < KCHUNK; kr++) {
            float a[8];
            #pragma unroll
            for (int i = 0; i < 8; i++)
                a[i] = As[(tw * 8 + i) * IN_DIM + kk + kr];  // warp-broadcast
            float4 b0 = *(const float4*)&Bs[kr * OUT_DIM + tn * 8];
            float4 b1 = *(const float4*)&Bs[kr * OUT_DIM + tn * 8 + 4];
            float b[8] = { b0.x, b0.y, b0.z, b0.w, b1.x, b1.y, b1.z, b1.w };
            #pragma unroll
            for (int i = 0; i < 8; i++)
                #pragma unroll
                for (int j = 0; j < 8; j++)
                    acc[i][j] = fmaf(a[i], b[j], acc[i][j]);
        }
    }

    // ---- Epilogue: relu + store ----
    #pragma unroll
    for (int i = 0; i < 8; i++) {
        int row = mbase + tw * 8 + i;
        if (row < N_NODES) {
            float4 o0, o1;
            o0.x = fmaxf(acc[i][0], 0.f); o0.y = fmaxf(acc[i][1], 0.f);
            o0.z = fmaxf(acc[i][2], 0.f); o0.w = fmaxf(acc[i][3], 0.f);
            o1.x = fmaxf(acc[i][4], 0.f); o1.y = fmaxf(acc[i][5], 0.f);
            o1.z = fmaxf(acc[i][6], 0.f); o1.w = fmaxf(acc[i][7], 0.f);
            ((float4*)out)[row * (OUT_DIM / 4) + tn * 2 + 0] = o0;
            ((float4*)out)[row * (OUT_DIM / 4) + tn * 2 + 1] = o1;
        }
    }
}

// ---------------------------------------------------------------------------
extern "C" void kernel_launch(void* const* d_in, const int* in_sizes, int n_in,
                              void* d_out, int out_size) {
    const float* feat = (const float*)d_in[0];
    const float* W    = (const float*)d_in[1];
    const void*  src  = d_in[2];
    const void*  dst  = d_in[3];
    float*       out  = (float*)d_out;

    detect_kernel<<<1, 32>>>((const int*)src);
    zero_kernel<<<512, 256>>>();
    scatter_kernel<<<2048, 256>>>((const float4*)feat, src, dst);

    cudaFuncSetAttribute(fused_gemm,
                         cudaFuncAttributeMaxDynamicSharedMemorySize, GEMM_SMEM);
    fused_gemm<<<(N_NODES + TM - 1) / TM, 256, GEMM_SMEM>>>(feat, W, out);
}

// round 3
// speedup vs baseline: 1.3235x; 1.3235x over previous
#include <cuda_runtime.h>
#include <cuda_bf16.h>
#include <cstdint>

#define N_NODES 50000
#define N_EDGES 800000
#define IN_DIM  128
#define OUT_DIM 256

// ------------------------- device scratch -------------------------
__device__ float g_msg[N_NODES * IN_DIM];   // neighbor feature sums
__device__ float g_deg[N_NODES];            // in-degree
__device__ int   g_is64;

// ------------------------- helpers -------------------------
__device__ __forceinline__ float to_tf32(float x) {
    float r;
    asm("cvt.rna.tf32.f32 %0, %1;" : "=f"(r) : "f"(x));
    return r;
}

// ------------------------- index dtype detect -------------------------
__global__ void detect_kernel(const int* __restrict__ idx) {
    int l = threadIdx.x;
    int v0 = idx[2 * l + 1];
    int v1 = idx[2 * (l + 32) + 1];
    unsigned ok = __ballot_sync(0xFFFFFFFFu, (v0 == 0) && (v1 == 0));
    if (l == 0) g_is64 = (ok == 0xFFFFFFFFu) ? 1 : 0;
}

// ------------------------- zero accumulators -------------------------
__global__ void zero_kernel() {
    int tid    = blockIdx.x * blockDim.x + threadIdx.x;
    int stride = gridDim.x * blockDim.x;
    float4* m4 = (float4*)g_msg;
    int total4 = (N_NODES * IN_DIM) / 4;
    float4 z = make_float4(0.f, 0.f, 0.f, 0.f);
    for (int i = tid; i < total4; i += stride) m4[i] = z;
    for (int i = tid; i < N_NODES; i += stride) g_deg[i] = 0.f;
}

// ------------------------- edge scatter (L2-cap bound; unchanged) -------------------------
__global__ void scatter_kernel(const float4* __restrict__ feat4,
                               const void* __restrict__ srcp,
                               const void* __restrict__ dstp) {
    int lane   = threadIdx.x & 31;
    int warp   = (blockIdx.x * blockDim.x + threadIdx.x) >> 5;
    int nwarps = (gridDim.x * blockDim.x) >> 5;
    int is64   = g_is64;
    const long long* s64 = (const long long*)srcp;
    const long long* d64 = (const long long*)dstp;
    const int*       s32 = (const int*)srcp;
    const int*       d32 = (const int*)dstp;

    for (int e = warp; e < N_EDGES; e += nwarps) {
        int s, d;
        if (is64) { s = (int)s64[e]; d = (int)d64[e]; }
        else      { s = s32[e];      d = d32[e];      }
        float4 v = feat4[s * (IN_DIM / 4) + lane];
        float* p = &g_msg[d * IN_DIM + lane * 4];
        asm volatile("red.global.add.v4.f32 [%0], {%1,%2,%3,%4};"
                     :: "l"(p), "f"(v.x), "f"(v.y), "f"(v.z), "f"(v.w)
                     : "memory");
        if (lane == 0) atomicAdd(&g_deg[d], 1.0f);
    }
}

// ---------------------------------------------------------------------------
// tf32 mma.sync GEMM: out = relu( ((feat + msg/max(deg,1)) * 0.5) @ W )
// CTA tile: 128 rows x 128 cols (grid.y = 2 halves of OUT_DIM), K=128 one-shot.
// smem: A [128][136] fp32(tf32-rounded), B [128][136]. Pad 136 -> stride==8 mod 32
// -> conflict-free fragment loads. 8 warps, warp tile 64x32 (4 m16 x 4 n8).
// ---------------------------------------------------------------------------
#define PAD 136
#define GEMM_SMEM (2 * 128 * PAD * 4)   // 139264 B

extern __shared__ float sm_dyn[];

__global__ __launch_bounds__(256) void gemm_mma(const float* __restrict__ feat,
                                                const float* __restrict__ W,
                                                float* __restrict__ out) {
    float* As = sm_dyn;               // [128][PAD]
    float* Bs = sm_dyn + 128 * PAD;   // [128][PAD] (k-major: Bs[k][n])
    int t     = threadIdx.x;
    int wid   = t >> 5;
    int lane  = t & 31;
    int g     = lane >> 2;   // group id 0..7
    int tq    = lane & 3;    // thread-in-group 0..3
    int mbase = blockIdx.x * 128;
    int nbase = blockIdx.y * 128;

    // ---- A tile: x = feat*0.5 + msg*(0.5/max(deg,1)), tf32-rounded ----
    #pragma unroll
    for (int it = 0; it < 16; it++) {
        int f   = t + it * 256;
        int row = f >> 5;          // 0..127
        int kq  = f & 31;          // float4 col
        int grow = mbase + row;
        float4 a = make_float4(0.f, 0.f, 0.f, 0.f);
        if (grow < N_NODES) {
            float4 fv = ((const float4*)feat)[grow * 32 + kq];
            float4 mv = ((const float4*)g_msg)[grow * 32 + kq];
            float inv = 0.5f / fmaxf(g_deg[grow], 1.0f);
            a.x = to_tf32(fv.x * 0.5f + mv.x * inv);
            a.y = to_tf32(fv.y * 0.5f + mv.y * inv);
            a.z = to_tf32(fv.z * 0.5f + mv.z * inv);
            a.w = to_tf32(fv.w * 0.5f + mv.w * inv);
        }
        *(float4*)&As[row * PAD + kq * 4] = a;
    }

    // ---- B tile: W[k][nbase..nbase+128), tf32-rounded (W already k-major) ----
    #pragma unroll
    for (int it = 0; it < 16; it++) {
        int f  = t + it * 256;
        int k  = f >> 5;           // 0..127
        int nq = f & 31;           // float4 col within half
        float4 b = *(const float4*)&W[k * OUT_DIM + nbase + nq * 4];
        b.x = to_tf32(b.x); b.y = to_tf32(b.y);
        b.z = to_tf32(b.z); b.w = to_tf32(b.w);
        *(float4*)&Bs[k * PAD + nq * 4] = b;
    }
    __syncthreads();

    // ---- warp tiles: wm in {0,1} (64 rows), wn in {0..3} (32 cols) ----
    int wm = wid & 1;
    int wn = wid >> 1;
    int arow = wm * 64 + g;        // + i*16 (+8 for upper frag)
    int bcol = wn * 32 + g;        // + j*8

    float c[4][4][4];
    #pragma unroll
    for (int i = 0; i < 4; i++)
        #pragma unroll
        for (int j = 0; j < 4; j++)
            c[i][j][0] = c[i][j][1] = c[i][j][2] = c[i][j][3] = 0.f;

    #pragma unroll 4
    for (int k0 = 0; k0 < 128; k0 += 8) {
        uint32_t a[4][4];
        #pragma unroll
        for (int i = 0; i < 4; i++) {
            const float* pa = &As[(arow + i * 16) * PAD + k0 + tq];
            a[i][0] = __float_as_uint(pa[0]);
            a[i][1] = __float_as_uint(pa[8 * PAD]);
            a[i][2] = __float_as_uint(pa[4]);
            a[i][3] = __float_as_uint(pa[8 * PAD + 4]);
        }
        uint32_t b[4][2];
        #pragma unroll
        for (int j = 0; j < 4; j++) {
            const float* pb = &Bs[(k0 + tq) * PAD + bcol + j * 8];
            b[j][0] = __float_as_uint(pb[0]);
            b[j][1] = __float_as_uint(pb[4 * PAD]);
        }
        #pragma unroll
        for (int i = 0; i < 4; i++)
            #pragma unroll
            for (int j = 0; j < 4; j++) {
                asm volatile(
                    "mma.sync.aligned.m16n8k8.row.col.f32.tf32.tf32.f32 "
                    "{%0,%1,%2,%3}, {%4,%5,%6,%7}, {%8,%9}, {%0,%1,%2,%3};"
                    : "+f"(c[i][j][0]), "+f"(c[i][j][1]),
                      "+f"(c[i][j][2]), "+f"(c[i][j][3])
                    : "r"(a[i][0]), "r"(a[i][1]), "r"(a[i][2]), "r"(a[i][3]),
                      "r"(b[j][0]), "r"(b[j][1]));
            }
    }

    // ---- epilogue: relu + float2 stores ----
    #pragma unroll
    for (int i = 0; i < 4; i++) {
        int r0 = mbase + wm * 64 + i * 16 + g;
        int r1 = r0 + 8;
        #pragma unroll
        for (int j = 0; j < 4; j++) {
            int col = nbase + wn * 32 + j * 8 + 2 * tq;
            if (r0 < N_NODES) {
                float2 v = make_float2(fmaxf(c[i][j][0], 0.f),
                                       fmaxf(c[i][j][1], 0.f));
                *(float2*)&out[r0 * OUT_DIM + col] = v;
            }
            if (r1 < N_NODES) {
                float2 v = make_float2(fmaxf(c[i][j][2], 0.f),
                                       fmaxf(c[i][j][3], 0.f));
                *(float2*)&out[r1 * OUT_DIM + col] = v;
            }
        }
    }
}

// ---------------------------------------------------------------------------
extern "C" void kernel_launch(void* const* d_in, const int* in_sizes, int n_in,
                              void* d_out, int out_size) {
    const float* feat = (const float*)d_in[0];
    const float* W    = (const float*)d_in[1];
    const void*  src  = d_in[2];
    const void*  dst  = d_in[3];
    float*       out  = (float*)d_out;

    detect_kernel<<<1, 32>>>((const int*)src);
    zero_kernel<<<512, 256>>>();
    scatter_kernel<<<2048, 256>>>((const float4*)feat, src, dst);

    cudaFuncSetAttribute(gemm_mma,
                         cudaFuncAttributeMaxDynamicSharedMemorySize, GEMM_SMEM);
    dim3 grid((N_NODES + 127) / 128, 2);
    gemm_mma<<<grid, 256, GEMM_SMEM>>>(feat, W, out);
}

// round 4
// speedup vs baseline: 2.1510x; 1.6252x over previous
#include <cuda_runtime.h>
#include <cuda_bf16.h>
#include <cstdint>

#define N_NODES 50000
#define N_EDGES 800000
#define IN_DIM  128
#define OUT_DIM 256

// ------------------------- device scratch -------------------------
__device__ int   g_degi[N_NODES];           // in-degree (int)
__device__ int   g_off[N_NODES];            // CSR row offsets (exclusive scan)
__device__ int   g_cur[N_NODES];            // fill cursors
__device__ int   g_part[256];               // scan partials
__device__ int   g_adj[N_EDGES];            // CSR adjacency (src ids grouped by dst)
__device__ float g_x[N_NODES * IN_DIM];     // fused GEMM input, tf32-rounded
__device__ float g_Wt[OUT_DIM * IN_DIM];    // W transposed [n][k], tf32-rounded
__device__ int   g_is64;

// ------------------------- helpers -------------------------
__device__ __forceinline__ float to_tf32(float x) {
    float r;
    asm("cvt.rna.tf32.f32 %0, %1;" : "=f"(r) : "f"(x));
    return r;
}
__device__ __forceinline__ uint32_t smem_u32(const void* p) {
    uint32_t a;
    asm("{ .reg .u64 t; cvta.to.shared.u64 t, %1; cvt.u32.u64 %0, t; }"
        : "=r"(a) : "l"(p));
    return a;
}
__device__ __forceinline__ void cp16(uint32_t dst, const void* src, int srcsz) {
    asm volatile("cp.async.cg.shared.global [%0], [%1], 16, %2;"
                 :: "r"(dst), "l"(src), "r"(srcsz) : "memory");
}
__device__ __forceinline__ int load_idx(const void* p, int e, int is64) {
    return is64 ? (int)((const long long*)p)[e] : ((const int*)p)[e];
}

// ------------------------- index dtype detect -------------------------
__global__ void detect_kernel(const int* __restrict__ idx) {
    int l = threadIdx.x;
    int v0 = idx[2 * l + 1];
    int v1 = idx[2 * (l + 32) + 1];
    unsigned ok = __ballot_sync(0xFFFFFFFFu, (v0 == 0) && (v1 == 0));
    if (l == 0) g_is64 = (ok == 0xFFFFFFFFu) ? 1 : 0;
}

// ------------------------- prep: zero degrees + round/transpose W -------------------------
__global__ void prep_kernel(const float* __restrict__ W) {
    int i = blockIdx.x * blockDim.x + threadIdx.x;
    if (i < N_NODES) g_degi[i] = 0;
    if (i < IN_DIM * OUT_DIM) {
        int k = i >> 8;
        int n = i & 255;
        g_Wt[n * IN_DIM + k] = to_tf32(W[i]);   // coalesced read, strided write (131KB, cheap)
    }
}

// ------------------------- degree histogram -------------------------
__global__ void hist_kernel(const void* __restrict__ dstp) {
    int e = blockIdx.x * blockDim.x + threadIdx.x;
    if (e < N_EDGES) atomicAdd(&g_degi[load_idx(dstp, e, g_is64)], 1);
}

// ------------------------- exclusive scan (3 phases, Hillis-Steele) -------------------------
__global__ void scan1_kernel() {
    __shared__ int s[2][256];
    int b = blockIdx.x, tid = threadIdx.x;
    int i = b * 256 + tid;
    int v = (i < N_NODES) ? g_degi[i] : 0;
    int p = 0;
    s[0][tid] = v;
    __syncthreads();
    for (int o = 1; o < 256; o <<= 1) {
        int val = s[p][tid] + ((tid >= o) ? s[p][tid - o] : 0);
        s[p ^ 1][tid] = val;
        p ^= 1;
        __syncthreads();
    }
    int incl = s[p][tid];
    if (i < N_NODES) g_off[i] = incl - v;
    if (tid == 255) g_part[b] = incl;
}

__global__ void scan2_kernel(int nparts) {
    __shared__ int s[2][256];
    int tid = threadIdx.x;
    int v = (tid < nparts) ? g_part[tid] : 0;
    int p = 0;
    s[0][tid] = v;
    __syncthreads();
    for (int o = 1; o < 256; o <<= 1) {
        int val = s[p][tid] + ((tid >= o) ? s[p][tid - o] : 0);
        s[p ^ 1][tid] = val;
        p ^= 1;
        __syncthreads();
    }
    if (tid < nparts) g_part[tid] = s[p][tid] - v;   // exclusive
}

__global__ void scan3_kernel() {
    int b = blockIdx.x, tid = threadIdx.x;
    int i = b * 256 + tid;
    if (i < N_NODES) {
        int o = g_off[i] + g_part[b];
        g_off[i] = o;
        g_cur[i] = o;
    }
}

// ------------------------- CSR bucket fill -------------------------
__global__ void fill_kernel(const void* __restrict__ srcp,
                            const void* __restrict__ dstp) {
    int e = blockIdx.x * blockDim.x + threadIdx.x;
    if (e < N_EDGES) {
        int is64 = g_is64;
        int s = load_idx(srcp, e, is64);
        int d = load_idx(dstp, e, is64);
        int pos = atomicAdd(&g_cur[d], 1);
        g_adj[pos] = s;
    }
}

// ------------------------- gather + fuse + tf32 round -------------------------
// One warp per node. Lane l owns float4 l of the 128-dim row.
__global__ void gather_kernel(const float4* __restrict__ feat4) {
    int lane = threadIdx.x & 31;
    int node = (blockIdx.x * blockDim.x + threadIdx.x) >> 5;   // grid sized exactly
    int start = g_off[node];
    int deg   = g_degi[node];

    float4 acc = make_float4(0.f, 0.f, 0.f, 0.f);
    for (int base = 0; base < deg; base += 32) {
        int rem = deg - base;
        int a_  = 0;
        if (lane < rem) a_ = g_adj[start + base + lane];
        int cnt = min(rem, 32);
        int i = 0;
        for (; i + 4 <= cnt; i += 4) {
            int s0 = __shfl_sync(0xFFFFFFFFu, a_, i);
            int s1 = __shfl_sync(0xFFFFFFFFu, a_, i + 1);
            int s2 = __shfl_sync(0xFFFFFFFFu, a_, i + 2);
            int s3 = __shfl_sync(0xFFFFFFFFu, a_, i + 3);
            float4 f0 = feat4[s0 * 32 + lane];
            float4 f1 = feat4[s1 * 32 + lane];
            float4 f2 = feat4[s2 * 32 + lane];
            float4 f3 = feat4[s3 * 32 + lane];
            acc.x += f0.x + f1.x + f2.x + f3.x;
            acc.y += f0.y + f1.y + f2.y + f3.y;
            acc.z += f0.z + f1.z + f2.z + f3.z;
            acc.w += f0.w + f1.w + f2.w + f3.w;
        }
        for (; i < cnt; i++) {
            int s = __shfl_sync(0xFFFFFFFFu, a_, i);
            float4 f = feat4[s * 32 + lane];
            acc.x += f.x; acc.y += f.y; acc.z += f.z; acc.w += f.w;
        }
    }

    float inv = 0.5f / fmaxf((float)deg, 1.0f);
    float4 fv = feat4[node * 32 + lane];
    float4 x;
    x.x = to_tf32(fv.x * 0.5f + acc.x * inv);
    x.y = to_tf32(fv.y * 0.5f + acc.y * inv);
    x.z = to_tf32(fv.z * 0.5f + acc.z * inv);
    x.w = to_tf32(fv.w * 0.5f + acc.w * inv);
    ((float4*)g_x)[node * 32 + lane] = x;
}

// ---------------------------------------------------------------------------
// tf32 mma.sync GEMM: out = relu( g_x @ W )   [50000x128] @ [128x256]
// CTA: 512 threads (16 warps), tile M=128 x N=256, K=128 one-shot via cp.async.
// smem: As[128][132] k-major, Bs[256][132] n-major (g_Wt rows contiguous).
// PAD=132 -> fragment LDS bank = (4g+tq) mod 32 -> conflict-free.
// Warp tile 64x32: wm=wid&1 (M half), wn=wid>>1 (N/32), 4x4 m16n8k8 frags.
// ---------------------------------------------------------------------------
#define PADT 132
#define A_BYTES (128 * PADT * 4)             // 67584
#define B_BYTES (OUT_DIM * PADT * 4)         // 135168
#define GEMM_SMEM (A_BYTES + B_BYTES)        // 202752

extern __shared__ float sm_dyn[];

__global__ __launch_bounds__(512, 1) void gemm_mma(float* __restrict__ out) {
    float* As = sm_dyn;                 // [128][PADT]
    float* Bs = sm_dyn + 128 * PADT;    // [256][PADT]  (n-major)
    uint32_t sA = smem_u32(As);
    uint32_t sB = smem_u32(Bs);
    int t     = threadIdx.x;
    int wid   = t >> 5;
    int lane  = t & 31;
    int g     = lane >> 2;
    int tq    = lane & 3;
    int mbase = blockIdx.x * 128;

    // ---- async loads: A (4096 f4, 8/thread), B (8192 f4, 16/thread) ----
    #pragma unroll
    for (int it = 0; it < 8; it++) {
        int f   = t + it * 512;
        int row = f >> 5;
        int kq  = f & 31;
        int grow = mbase + row;
        int ok   = (grow < N_NODES) ? 16 : 0;
        int srow = (grow < N_NODES) ? grow : 0;
        cp16(sA + (row * PADT + kq * 4) * 4, &g_x[srow * IN_DIM + kq * 4], ok);
    }
    #pragma unroll
    for (int it = 0; it < 16; it++) {
        int f  = t + it * 512;
        int n  = f >> 5;
        int kq = f & 31;
        cp16(sB + (n * PADT + kq * 4) * 4, &g_Wt[n * IN_DIM + kq * 4], 16);
    }
    asm volatile("cp.async.commit_group;" ::: "memory");
    asm volatile("cp.async.wait_group 0;" ::: "memory");
    __syncthreads();

    // ---- warp tiles ----
    int wm = wid & 1;        // 0..1 : M half (64 rows)
    int wn = wid >> 1;       // 0..7 : N block (32 cols)
    int arow = wm * 64 + g;
    int bcol = wn * 32 + g;

    float c[4][4][4];
    #pragma unroll
    for (int i = 0; i < 4; i++)
        #pragma unroll
        for (int j = 0; j < 4; j++)
            c[i][j][0] = c[i][j][1] = c[i][j][2] = c[i][j][3] = 0.f;

    #pragma unroll 4
    for (int k0 = 0; k0 < 128; k0 += 8) {
        uint32_t a[4][4];
        #pragma unroll
        for (int i = 0; i < 4; i++) {
            const float* pa = &As[(arow + i * 16) * PADT + k0 + tq];
            a[i][0] = __float_as_uint(pa[0]);
            a[i][1] = __float_as_uint(pa[8 * PADT]);
            a[i][2] = __float_as_uint(pa[4]);
            a[i][3] = __float_as_uint(pa[8 * PADT + 4]);
        }
        uint32_t b[4][2];
        #pragma unroll
        for (int j = 0; j < 4; j++) {
            const float* pb = &Bs[(bcol + j * 8) * PADT + k0 + tq];
            b[j][0] = __float_as_uint(pb[0]);
            b[j][1] = __float_as_uint(pb[4]);
        }
        #pragma unroll
        for (int i = 0; i < 4; i++)
            #pragma unroll
            for (int j = 0; j < 4; j++) {
                asm volatile(
                    "mma.sync.aligned.m16n8k8.row.col.f32.tf32.tf32.f32 "
                    "{%0,%1,%2,%3}, {%4,%5,%6,%7}, {%8,%9}, {%0,%1,%2,%3};"
                    : "+f"(c[i][j][0]), "+f"(c[i][j][1]),
                      "+f"(c[i][j][2]), "+f"(c[i][j][3])
                    : "r"(a[i][0]), "r"(a[i][1]), "r"(a[i][2]), "r"(a[i][3]),
                      "r"(b[j][0]), "r"(b[j][1]));
            }
    }

    // ---- epilogue: relu + float2 stores ----
    #pragma unroll
    for (int i = 0; i < 4; i++) {
        int r0 = mbase + wm * 64 + i * 16 + g;
        int r1 = r0 + 8;
        #pragma unroll
        for (int j = 0; j < 4; j++) {
            int col = wn * 32 + j * 8 + 2 * tq;
            if (r0 < N_NODES) {
                float2 v = make_float2(fmaxf(c[i][j][0], 0.f),
                                       fmaxf(c[i][j][1], 0.f));
                *(float2*)&out[r0 * OUT_DIM + col] = v;
            }
            if (r1 < N_NODES) {
                float2 v = make_float2(fmaxf(c[i][j][2], 0.f),
                                       fmaxf(c[i][j][3], 0.f));
                *(float2*)&out[r1 * OUT_DIM + col] = v;
            }
        }
    }
}

// ---------------------------------------------------------------------------
extern "C" void kernel_launch(void* const* d_in, const int* in_sizes, int n_in,
                              void* d_out, int out_size) {
    const float* feat = (const float*)d_in[0];
    const float* W    = (const float*)d_in[1];
    const void*  src  = d_in[2];
    const void*  dst  = d_in[3];
    float*       out  = (float*)d_out;

    const int NB = (N_NODES + 255) / 256;      // 196

    detect_kernel<<<1, 32>>>((const int*)src);
    prep_kernel<<<NB, 256>>>(W);
    hist_kernel<<<(N_EDGES + 255) / 256, 256>>>(dst);
    scan1_kernel<<<NB, 256>>>();
    scan2_kernel<<<1, 256>>>(NB);
    scan3_kernel<<<NB, 256>>>();
    fill_kernel<<<(N_EDGES + 255) / 256, 256>>>(src, dst);
    gather_kernel<<<(N_NODES * 32) / 256, 256>>>((const float4*)feat);

    cudaFuncSetAttribute(gemm_mma,
                         cudaFuncAttributeMaxDynamicSharedMemorySize, GEMM_SMEM);
    gemm_mma<<<(N_NODES + 127) / 128, 512, GEMM_SMEM>>>(out);
}

// round 5
// speedup vs baseline: 2.1685x; 1.0082x over previous
#include <cuda_runtime.h>
#include <cuda_bf16.h>
#include <cstdint>

#define N_NODES 50000
#define N_EDGES 800000
#define IN_DIM  128
#define OUT_DIM 256

// ------------------------- device scratch -------------------------
__device__ int   g_degi[N_NODES];           // in-degree (int)
__device__ int   g_off[N_NODES];            // CSR row offsets (exclusive scan)
__device__ int   g_cur[N_NODES];            // fill cursors
__device__ int   g_part[64];                // scan partials (49 used)
__device__ int   g_adj[N_EDGES];            // CSR adjacency (src ids grouped by dst)
__device__ float g_x[N_NODES * IN_DIM];     // fused GEMM input, tf32-rounded
__device__ float g_Wt[OUT_DIM * IN_DIM];    // W transposed [n][k], tf32-rounded
__device__ int   g_is64;

// ------------------------- helpers -------------------------
__device__ __forceinline__ float to_tf32(float x) {
    float r;
    asm("cvt.rna.tf32.f32 %0, %1;" : "=f"(r) : "f"(x));
    return r;
}
__device__ __forceinline__ uint32_t smem_u32(const void* p) {
    uint32_t a;
    asm("{ .reg .u64 t; cvta.to.shared.u64 t, %1; cvt.u32.u64 %0, t; }"
        : "=r"(a) : "l"(p));
    return a;
}
__device__ __forceinline__ void cp16(uint32_t dst, const void* src) {
    asm volatile("cp.async.cg.shared.global [%0], [%1], 16;"
                 :: "r"(dst), "l"(src) : "memory");
}
__device__ __forceinline__ void cp16z(uint32_t dst, const void* src, int srcsz) {
    asm volatile("cp.async.cg.shared.global [%0], [%1], 16, %2;"
                 :: "r"(dst), "l"(src), "r"(srcsz) : "memory");
}
__device__ __forceinline__ int load_idx(const void* p, int e, int is64) {
    return is64 ? (int)((const long long*)p)[e] : ((const int*)p)[e];
}

// ------------------------- prep: detect dtype + zero degrees + W transpose -------------------------
__global__ void prep_kernel(const float* __restrict__ W, const int* __restrict__ idx) {
    int i = blockIdx.x * blockDim.x + threadIdx.x;
    if (blockIdx.x == 0 && threadIdx.x < 32) {
        int l = threadIdx.x;
        int v0 = idx[2 * l + 1];
        int v1 = idx[2 * (l + 32) + 1];
        unsigned ok = __ballot_sync(0xFFFFFFFFu, (v0 == 0) && (v1 == 0));
        if (l == 0) g_is64 = (ok == 0xFFFFFFFFu) ? 1 : 0;
    }
    if (i < N_NODES) g_degi[i] = 0;
    if (i < IN_DIM * OUT_DIM) {
        int k = i >> 8;
        int n = i & 255;
        g_Wt[n * IN_DIM + k] = to_tf32(W[i]);
    }
}

// ------------------------- degree histogram -------------------------
__global__ void hist_kernel(const void* __restrict__ dstp) {
    int e = blockIdx.x * blockDim.x + threadIdx.x;
    if (e < N_EDGES) atomicAdd(&g_degi[load_idx(dstp, e, g_is64)], 1);
}

// ------------------------- exclusive scan (shfl-based, 1024-thread blocks) -------------------------
__device__ __forceinline__ int block_incl_scan(int v, int* ws, int tid) {
    int lane = tid & 31, wid = tid >> 5;
    int incl = v;
    #pragma unroll
    for (int o = 1; o < 32; o <<= 1) {
        int n = __shfl_up_sync(0xFFFFFFFFu, incl, o);
        if (lane >= o) incl += n;
    }
    if (lane == 31) ws[wid] = incl;
    __syncthreads();
    if (wid == 0) {
        int s = ws[lane];
        #pragma unroll
        for (int o = 1; o < 32; o <<= 1) {
            int n = __shfl_up_sync(0xFFFFFFFFu, s, o);
            if (lane >= o) s += n;
        }
        ws[lane] = s;
    }
    __syncthreads();
    return incl + ((wid > 0) ? ws[wid - 1] : 0);
}

__global__ void scan1_kernel() {
    __shared__ int ws[32];
    int b = blockIdx.x, tid = threadIdx.x;
    int i = b * 1024 + tid;
    int v = (i < N_NODES) ? g_degi[i] : 0;
    int incl = block_incl_scan(v, ws, tid);
    if (i < N_NODES) g_off[i] = incl - v;
    if (tid == 1023) g_part[b] = incl;
}

__global__ void scan2_kernel(int nparts) {
    __shared__ int ws[2];
    int t = threadIdx.x, lane = t & 31, wid = t >> 5;
    int v = (t < nparts) ? g_part[t] : 0;
    int incl = v;
    #pragma unroll
    for (int o = 1; o < 32; o <<= 1) {
        int n = __shfl_up_sync(0xFFFFFFFFu, incl, o);
        if (lane >= o) incl += n;
    }
    if (lane == 31) ws[wid] = incl;
    __syncthreads();
    int off = (wid == 1) ? ws[0] : 0;
    if (t < nparts) g_part[t] = off + incl - v;   // exclusive
}

__global__ void scan3_kernel() {
    int b = blockIdx.x, tid = threadIdx.x;
    int i = b * 1024 + tid;
    if (i < N_NODES) {
        int o = g_off[i] + g_part[b];
        g_off[i] = o;
        g_cur[i] = o;
    }
}

// ------------------------- CSR bucket fill -------------------------
__global__ void fill_kernel(const void* __restrict__ srcp,
                            const void* __restrict__ dstp) {
    int e = blockIdx.x * blockDim.x + threadIdx.x;
    if (e < N_EDGES) {
        int is64 = g_is64;
        int s = load_idx(srcp, e, is64);
        int d = load_idx(dstp, e, is64);
        int pos = atomicAdd(&g_cur[d], 1);
        g_adj[pos] = s;
    }
}

// ------------------------- gather + fuse + tf32 round (L2-floor bound) -------------------------
__global__ void gather_kernel(const float4* __restrict__ feat4) {
    int lane = threadIdx.x & 31;
    int node = (blockIdx.x * blockDim.x + threadIdx.x) >> 5;
    int start = g_off[node];
    int deg   = g_degi[node];

    float4 acc = make_float4(0.f, 0.f, 0.f, 0.f);
    for (int base = 0; base < deg; base += 32) {
        int rem = deg - base;
        int a_  = 0;
        if (lane < rem) a_ = g_adj[start + base + lane];
        int cnt = min(rem, 32);
        int i = 0;
        for (; i + 4 <= cnt; i += 4) {
            int s0 = __shfl_sync(0xFFFFFFFFu, a_, i);
            int s1 = __shfl_sync(0xFFFFFFFFu, a_, i + 1);
            int s2 = __shfl_sync(0xFFFFFFFFu, a_, i + 2);
            int s3 = __shfl_sync(0xFFFFFFFFu, a_, i + 3);
            float4 f0 = feat4[s0 * 32 + lane];
            float4 f1 = feat4[s1 * 32 + lane];
            float4 f2 = feat4[s2 * 32 + lane];
            float4 f3 = feat4[s3 * 32 + lane];
            acc.x += f0.x + f1.x + f2.x + f3.x;
            acc.y += f0.y + f1.y + f2.y + f3.y;
            acc.z += f0.z + f1.z + f2.z + f3.z;
            acc.w += f0.w + f1.w + f2.w + f3.w;
        }
        for (; i < cnt; i++) {
            int s = __shfl_sync(0xFFFFFFFFu, a_, i);
            float4 f = feat4[s * 32 + lane];
            acc.x += f.x; acc.y += f.y; acc.z += f.z; acc.w += f.w;
        }
    }

    float inv = 0.5f / fmaxf((float)deg, 1.0f);
    float4 fv = feat4[node * 32 + lane];
    float4 x;
    x.x = to_tf32(fv.x * 0.5f + acc.x * inv);
    x.y = to_tf32(fv.y * 0.5f + acc.y * inv);
    x.z = to_tf32(fv.z * 0.5f + acc.z * inv);
    x.w = to_tf32(fv.w * 0.5f + acc.w * inv);
    ((float4*)g_x)[node * 32 + lane] = x;
}

// ---------------------------------------------------------------------------
// tf32 mma.sync GEMM: out = relu( g_x @ W )
// CTA tile: M=64 x N=128 (grid.y=2), K=128 one-shot. 256 threads (8 warps).
// smem = 101376B -> 2 CTAs/SM. Warp tile 32x32: wm=wid&1, wn=wid>>1.
// PADT=132 -> conflict-free fragment LDS (bank = (4g+tq)%32, all distinct).
// ---------------------------------------------------------------------------
#define PADT 132
#define A_ROWS 64
#define B_ROWS 128
#define GEMM_SMEM ((A_ROWS + B_ROWS) * PADT * 4)   // 101376

extern __shared__ float sm_dyn[];

__global__ __launch_bounds__(256, 2) void gemm_mma(float* __restrict__ out) {
    float* As = sm_dyn;                   // [64][PADT]  k-major
    float* Bs = sm_dyn + A_ROWS * PADT;   // [128][PADT] n-major
    uint32_t sA = smem_u32(As);
    uint32_t sB = smem_u32(Bs);
    int t     = threadIdx.x;
    int wid   = t >> 5;
    int lane  = t & 31;
    int g     = lane >> 2;
    int tq    = lane & 3;
    int mbase = blockIdx.x * A_ROWS;
    int nbase = blockIdx.y * B_ROWS;

    // ---- async loads: A (2048 f4, 8/thread), B (4096 f4, 16/thread) ----
    #pragma unroll
    for (int it = 0; it < 8; it++) {
        int f   = t + it * 256;
        int row = f >> 5;
        int kq  = f & 31;
        int grow = mbase + row;
        int ok   = (grow < N_NODES) ? 16 : 0;
        int srow = (grow < N_NODES) ? grow : 0;
        cp16z(sA + (row * PADT + kq * 4) * 4, &g_x[srow * IN_DIM + kq * 4], ok);
    }
    #pragma unroll
    for (int it = 0; it < 16; it++) {
        int f  = t + it * 256;
        int n  = f >> 5;
        int kq = f & 31;
        cp16(sB + (n * PADT + kq * 4) * 4, &g_Wt[(nbase + n) * IN_DIM + kq * 4]);
    }
    asm volatile("cp.async.commit_group;" ::: "memory");
    asm volatile("cp.async.wait_group 0;" ::: "memory");
    __syncthreads();

    // ---- warp tiles: wm in {0,1} (32 rows), wn in {0..3} (32 cols) ----
    int wm = wid & 1;
    int wn = wid >> 1;
    int arow = wm * 32 + g;
    int bcol = wn * 32 + g;

    float c[2][4][4];
    #pragma unroll
    for (int i = 0; i < 2; i++)
        #pragma unroll
        for (int j = 0; j < 4; j++)
            c[i][j][0] = c[i][j][1] = c[i][j][2] = c[i][j][3] = 0.f;

    #pragma unroll 4
    for (int k0 = 0; k0 < 128; k0 += 8) {
        uint32_t a[2][4];
        #pragma unroll
        for (int i = 0; i < 2; i++) {
            const float* pa = &As[(arow + i * 16) * PADT + k0 + tq];
            a[i][0] = __float_as_uint(pa[0]);
            a[i][1] = __float_as_uint(pa[8 * PADT]);
            a[i][2] = __float_as_uint(pa[4]);
            a[i][3] = __float_as_uint(pa[8 * PADT + 4]);
        }
        uint32_t b[4][2];
        #pragma unroll
        for (int j = 0; j < 4; j++) {
            const float* pb = &Bs[(bcol + j * 8) * PADT + k0 + tq];
            b[j][0] = __float_as_uint(pb[0]);
            b[j][1] = __float_as_uint(pb[4]);
        }
        #pragma unroll
        for (int i = 0; i < 2; i++)
            #pragma unroll
            for (int j = 0; j < 4; j++) {
                asm volatile(
                    "mma.sync.aligned.m16n8k8.row.col.f32.tf32.tf32.f32 "
                    "{%0,%1,%2,%3}, {%4,%5,%6,%7}, {%8,%9}, {%0,%1,%2,%3};"
                    : "+f"(c[i][j][0]), "+f"(c[i][j][1]),
                      "+f"(c[i][j][2]), "+f"(c[i][j][3])
                    : "r"(a[i][0]), "r"(a[i][1]), "r"(a[i][2]), "r"(a[i][3]),
                      "r"(b[j][0]), "r"(b[j][1]));
            }
    }

    // ---- epilogue: relu + float2 stores ----
    #pragma unroll
    for (int i = 0; i < 2; i++) {
        int r0 = mbase + wm * 32 + i * 16 + g;
        int r1 = r0 + 8;
        #pragma unroll
        for (int j = 0; j < 4; j++) {
            int col = nbase + wn * 32 + j * 8 + 2 * tq;
            if (r0 < N_NODES) {
                float2 v = make_float2(fmaxf(c[i][j][0], 0.f),
                                       fmaxf(c[i][j][1], 0.f));
                *(float2*)&out[r0 * OUT_DIM + col] = v;
            }
            if (r1 < N_NODES) {
                float2 v = make_float2(fmaxf(c[i][j][2], 0.f),
                                       fmaxf(c[i][j][3], 0.f));
                *(float2*)&out[r1 * OUT_DIM + col] = v;
            }
        }
    }
}

// ---------------------------------------------------------------------------
extern "C" void kernel_launch(void* const* d_in, const int* in_sizes, int n_in,
                              void* d_out, int out_size) {
    const float* feat = (const float*)d_in[0];
    const float* W    = (const float*)d_in[1];
    const void*  src  = d_in[2];
    const void*  dst  = d_in[3];
    float*       out  = (float*)d_out;

    const int NB = (N_NODES + 1023) / 1024;    // 49

    prep_kernel<<<NB, 1024>>>(W, (const int*)src);
    hist_kernel<<<(N_EDGES + 255) / 256, 256>>>(dst);
    scan1_kernel<<<NB, 1024>>>();
    scan2_kernel<<<1, 64>>>(NB);
    scan3_kernel<<<NB, 1024>>>();
    fill_kernel<<<(N_EDGES + 255) / 256, 256>>>(src, dst);
    gather_kernel<<<(N_NODES * 32) / 256, 256>>>((const float4*)feat);

    cudaFuncSetAttribute(gemm_mma,
                         cudaFuncAttributeMaxDynamicSharedMemorySize, GEMM_SMEM);
    dim3 grid((N_NODES + A_ROWS - 1) / A_ROWS, 2);
    gemm_mma<<<grid, 256, GEMM_SMEM>>>(out);
}

// round 6
// speedup vs baseline: 2.2144x; 1.0212x over previous
#include <cuda_runtime.h>
#include <cuda_bf16.h>
#include <cstdint>

#define N_NODES 50000
#define N_EDGES 800000
#define IN_DIM  128
#define OUT_DIM 256

// ------------------------- device scratch -------------------------
__device__ int   g_degi[N_NODES];                 // in-degree (int)
__device__ int   g_off[N_NODES];                  // CSR row offsets
__device__ int   g_cur[N_NODES];                  // fill cursors
__device__ unsigned long long g_scanpack[64];     // lookback: flag(bit63)|total
__device__ int   g_adj[N_EDGES];                  // CSR adjacency
__device__ __nv_bfloat162 g_featb[N_NODES * 64];  // feat in bf16 (gather source)
__device__ float g_x[N_NODES * IN_DIM];           // fused GEMM input (tf32-rounded)
__device__ float g_Wt[OUT_DIM * IN_DIM];          // W^T [n][k], tf32-rounded
__device__ int   g_is64;

// ------------------------- helpers -------------------------
__device__ __forceinline__ float to_tf32(float x) {
    float r;
    asm("cvt.rna.tf32.f32 %0, %1;" : "=f"(r) : "f"(x));
    return r;
}
__device__ __forceinline__ uint32_t smem_u32(const void* p) {
    uint32_t a;
    asm("{ .reg .u64 t; cvta.to.shared.u64 t, %1; cvt.u32.u64 %0, t; }"
        : "=r"(a) : "l"(p));
    return a;
}
__device__ __forceinline__ void cp16(uint32_t dst, const void* src) {
    asm volatile("cp.async.cg.shared.global [%0], [%1], 16;"
                 :: "r"(dst), "l"(src) : "memory");
}
__device__ __forceinline__ void cp16z(uint32_t dst, const void* src, int srcsz) {
    asm volatile("cp.async.cg.shared.global [%0], [%1], 16, %2;"
                 :: "r"(dst), "l"(src), "r"(srcsz) : "memory");
}
__device__ __forceinline__ int load_idx(const void* p, int e, int is64) {
    return is64 ? (int)((const long long*)p)[e] : ((const int*)p)[e];
}

// ------------------------- prep: detect + zero + W^T + feat->bf16 -------------------------
// grid covers N_NODES*32 threads (one per float4 of feat)
__global__ void prep_kernel(const float* __restrict__ W, const int* __restrict__ idx,
                            const float4* __restrict__ feat4) {
    int i = blockIdx.x * blockDim.x + threadIdx.x;
    if (blockIdx.x == 0 && threadIdx.x < 32) {
        int l = threadIdx.x;
        int v0 = idx[2 * l + 1];
        int v1 = idx[2 * (l + 32) + 1];
        unsigned ok = __ballot_sync(0xFFFFFFFFu, (v0 == 0) && (v1 == 0));
        if (l == 0) g_is64 = (ok == 0xFFFFFFFFu) ? 1 : 0;
    }
    if (i < 64) g_scanpack[i] = 0ull;
    if (i < N_NODES) g_degi[i] = 0;
    if (i < IN_DIM * OUT_DIM) {
        int k = i >> 8;
        int n = i & 255;
        g_Wt[n * IN_DIM + k] = to_tf32(W[i]);
    }
    if (i < N_NODES * 32) {
        float4 f = feat4[i];
        g_featb[2 * i]     = __floats2bfloat162_rn(f.x, f.y);
        g_featb[2 * i + 1] = __floats2bfloat162_rn(f.z, f.w);
    }
}

// ------------------------- degree histogram -------------------------
__global__ void hist_kernel(const void* __restrict__ dstp) {
    int e = blockIdx.x * blockDim.x + threadIdx.x;
    if (e < N_EDGES) atomicAdd(&g_degi[load_idx(dstp, e, g_is64)], 1);
}

// ------------------------- single-kernel scan (decoupled lookback, 49 blocks) ------------
__device__ __forceinline__ int block_incl_scan(int v, int* ws, int tid) {
    int lane = tid & 31, wid = tid >> 5;
    int incl = v;
    #pragma unroll
    for (int o = 1; o < 32; o <<= 1) {
        int n = __shfl_up_sync(0xFFFFFFFFu, incl, o);
        if (lane >= o) incl += n;
    }
    if (lane == 31) ws[wid] = incl;
    __syncthreads();
    if (wid == 0) {
        int s = ws[lane];
        #pragma unroll
        for (int o = 1; o < 32; o <<= 1) {
            int n = __shfl_up_sync(0xFFFFFFFFu, s, o);
            if (lane >= o) s += n;
        }
        ws[lane] = s;
    }
    __syncthreads();
    return incl + ((wid > 0) ? ws[wid - 1] : 0);
}

__global__ void scan_kernel() {
    __shared__ int ws[32];
    __shared__ int s_prefix;
    int b = blockIdx.x, tid = threadIdx.x;
    int i = b * 1024 + tid;
    int v = (i < N_NODES) ? g_degi[i] : 0;
    int incl = block_incl_scan(v, ws, tid);
    int total = ws[31];    // grand total of this block (valid after scan's sync)

    if (tid == 0) {
        unsigned long long packed = 0x8000000000000000ull | (unsigned long long)(unsigned)total;
        atomicExch(&g_scanpack[b], packed);   // publish (atomic 64b: flag+value together)
    }
    if (tid < 32) {
        int lane = tid;
        int sum = 0;
        for (int base = 0; base < b; base += 32) {
            int idx = base + lane;
            if (idx < b) {
                unsigned long long p;
                do { p = atomicAdd(&g_scanpack[idx], 0ull); } while (!(p >> 63));
                sum += (int)(unsigned)(p & 0xFFFFFFFFull);
            }
        }
        #pragma unroll
        for (int o = 16; o; o >>= 1) sum += __shfl_xor_sync(0xFFFFFFFFu, sum, o);
        if (lane == 0) s_prefix = sum;
    }
    __syncthreads();
    if (i < N_NODES) {
        int off = s_prefix + incl - v;
        g_off[i] = off;
        g_cur[i] = off;
    }
}

// ------------------------- CSR bucket fill -------------------------
__global__ void fill_kernel(const void* __restrict__ srcp,
                            const void* __restrict__ dstp) {
    int e = blockIdx.x * blockDim.x + threadIdx.x;
    if (e < N_EDGES) {
        int is64 = g_is64;
        int s = load_idx(srcp, e, is64);
        int d = load_idx(dstp, e, is64);
        int pos = atomicAdd(&g_cur[d], 1);
        g_adj[pos] = s;
    }
}

// ------------------------- gather (bf16 neighbors, fp32 self) + tf32 round ------------
// One warp per node. Lane l owns dims [4l, 4l+4): uint2 of bf16 per neighbor row.
__global__ void gather_kernel(const float4* __restrict__ feat4) {
    int lane = threadIdx.x & 31;
    int node = (blockIdx.x * blockDim.x + threadIdx.x) >> 5;
    int start = g_off[node];
    int deg   = g_degi[node];
    const uint2* fb = (const uint2*)g_featb;   // row s: fb[s*32 + lane]

    float4 acc = make_float4(0.f, 0.f, 0.f, 0.f);
    for (int base = 0; base < deg; base += 32) {
        int rem = deg - base;
        int a_  = 0;
        if (lane < rem) a_ = g_adj[start + base + lane];
        int cnt = min(rem, 32);
        int i = 0;
        for (; i + 4 <= cnt; i += 4) {
            int s0 = __shfl_sync(0xFFFFFFFFu, a_, i);
            int s1 = __shfl_sync(0xFFFFFFFFu, a_, i + 1);
            int s2 = __shfl_sync(0xFFFFFFFFu, a_, i + 2);
            int s3 = __shfl_sync(0xFFFFFFFFu, a_, i + 3);
            uint2 u0 = fb[s0 * 32 + lane];
            uint2 u1 = fb[s1 * 32 + lane];
            uint2 u2 = fb[s2 * 32 + lane];
            uint2 u3 = fb[s3 * 32 + lane];
            float2 p;
            p = __bfloat1622float2(*(__nv_bfloat162*)&u0.x); acc.x += p.x; acc.y += p.y;
            p = __bfloat1622float2(*(__nv_bfloat162*)&u0.y); acc.z += p.x; acc.w += p.y;
            p = __bfloat1622float2(*(__nv_bfloat162*)&u1.x); acc.x += p.x; acc.y += p.y;
            p = __bfloat1622float2(*(__nv_bfloat162*)&u1.y); acc.z += p.x; acc.w += p.y;
            p = __bfloat1622float2(*(__nv_bfloat162*)&u2.x); acc.x += p.x; acc.y += p.y;
            p = __bfloat1622float2(*(__nv_bfloat162*)&u2.y); acc.z += p.x; acc.w += p.y;
            p = __bfloat1622float2(*(__nv_bfloat162*)&u3.x); acc.x += p.x; acc.y += p.y;
            p = __bfloat1622float2(*(__nv_bfloat162*)&u3.y); acc.z += p.x; acc.w += p.y;
        }
        for (; i < cnt; i++) {
            int s = __shfl_sync(0xFFFFFFFFu, a_, i);
            uint2 u = fb[s * 32 + lane];
            float2 p;
            p = __bfloat1622float2(*(__nv_bfloat162*)&u.x); acc.x += p.x; acc.y += p.y;
            p = __bfloat1622float2(*(__nv_bfloat162*)&u.y); acc.z += p.x; acc.w += p.y;
        }
    }

    float inv = 0.5f / fmaxf((float)deg, 1.0f);
    float4 fv = feat4[node * 32 + lane];       // self term exact fp32
    float4 x;
    x.x = to_tf32(fv.x * 0.5f + acc.x * inv);
    x.y = to_tf32(fv.y * 0.5f + acc.y * inv);
    x.z = to_tf32(fv.z * 0.5f + acc.z * inv);
    x.w = to_tf32(fv.w * 0.5f + acc.w * inv);
    ((float4*)g_x)[node * 32 + lane] = x;
}

// ---------------------------------------------------------------------------
// tf32 mma.sync GEMM (unchanged from R5): out = relu( g_x @ W )
// CTA M=64 x N=128 (grid.y=2), K=128 one-shot, 2 CTAs/SM.
// ---------------------------------------------------------------------------
#define PADT 132
#define A_ROWS 64
#define B_ROWS 128
#define GEMM_SMEM ((A_ROWS + B_ROWS) * PADT * 4)   // 101376

extern __shared__ float sm_dyn[];

__global__ __launch_bounds__(256, 2) void gemm_mma(float* __restrict__ out) {
    float* As = sm_dyn;
    float* Bs = sm_dyn + A_ROWS * PADT;
    uint32_t sA = smem_u32(As);
    uint32_t sB = smem_u32(Bs);
    int t     = threadIdx.x;
    int wid   = t >> 5;
    int lane  = t & 31;
    int g     = lane >> 2;
    int tq    = lane & 3;
    int mbase = blockIdx.x * A_ROWS;
    int nbase = blockIdx.y * B_ROWS;

    #pragma unroll
    for (int it = 0; it < 8; it++) {
        int f   = t + it * 256;
        int row = f >> 5;
        int kq  = f & 31;
        int grow = mbase + row;
        int ok   = (grow < N_NODES) ? 16 : 0;
        int srow = (grow < N_NODES) ? grow : 0;
        cp16z(sA + (row * PADT + kq * 4) * 4, &g_x[srow * IN_DIM + kq * 4], ok);
    }
    #pragma unroll
    for (int it = 0; it < 16; it++) {
        int f  = t + it * 256;
        int n  = f >> 5;
        int kq = f & 31;
        cp16(sB + (n * PADT + kq * 4) * 4, &g_Wt[(nbase + n) * IN_DIM + kq * 4]);
    }
    asm volatile("cp.async.commit_group;" ::: "memory");
    asm volatile("cp.async.wait_group 0;" ::: "memory");
    __syncthreads();

    int wm = wid & 1;
    int wn = wid >> 1;
    int arow = wm * 32 + g;
    int bcol = wn * 32 + g;

    float c[2][4][4];
    #pragma unroll
    for (int i = 0; i < 2; i++)
        #pragma unroll
        for (int j = 0; j < 4; j++)
            c[i][j][0] = c[i][j][1] = c[i][j][2] = c[i][j][3] = 0.f;

    #pragma unroll 4
    for (int k0 = 0; k0 < 128; k0 += 8) {
        uint32_t a[2][4];
        #pragma unroll
        for (int i = 0; i < 2; i++) {
            const float* pa = &As[(arow + i * 16) * PADT + k0 + tq];
            a[i][0] = __float_as_uint(pa[0]);
            a[i][1] = __float_as_uint(pa[8 * PADT]);
            a[i][2] = __float_as_uint(pa[4]);
            a[i][3] = __float_as_uint(pa[8 * PADT + 4]);
        }
        uint32_t b[4][2];
        #pragma unroll
        for (int j = 0; j < 4; j++) {
            const float* pb = &Bs[(bcol + j * 8) * PADT + k0 + tq];
            b[j][0] = __float_as_uint(pb[0]);
            b[j][1] = __float_as_uint(pb[4]);
        }
        #pragma unroll
        for (int i = 0; i < 2; i++)
            #pragma unroll
            for (int j = 0; j < 4; j++) {
                asm volatile(
                    "mma.sync.aligned.m16n8k8.row.col.f32.tf32.tf32.f32 "
                    "{%0,%1,%2,%3}, {%4,%5,%6,%7}, {%8,%9}, {%0,%1,%2,%3};"
                    : "+f"(c[i][j][0]), "+f"(c[i][j][1]),
                      "+f"(c[i][j][2]), "+f"(c[i][j][3])
                    : "r"(a[i][0]), "r"(a[i][1]), "r"(a[i][2]), "r"(a[i][3]),
                      "r"(b[j][0]), "r"(b[j][1]));
            }
    }

    #pragma unroll
    for (int i = 0; i < 2; i++) {
        int r0 = mbase + wm * 32 + i * 16 + g;
        int r1 = r0 + 8;
        #pragma unroll
        for (int j = 0; j < 4; j++) {
            int col = nbase + wn * 32 + j * 8 + 2 * tq;
            if (r0 < N_NODES) {
                float2 v = make_float2(fmaxf(c[i][j][0], 0.f),
                                       fmaxf(c[i][j][1], 0.f));
                *(float2*)&out[r0 * OUT_DIM + col] = v;
            }
            if (r1 < N_NODES) {
                float2 v = make_float2(fmaxf(c[i][j][2], 0.f),
                                       fmaxf(c[i][j][3], 0.f));
                *(float2*)&out[r1 * OUT_DIM + col] = v;
            }
        }
    }
}

// ---------------------------------------------------------------------------
extern "C" void kernel_launch(void* const* d_in, const int* in_sizes, int n_in,
                              void* d_out, int out_size) {
    const float* feat = (const float*)d_in[0];
    const float* W    = (const float*)d_in[1];
    const void*  src  = d_in[2];
    const void*  dst  = d_in[3];
    float*       out  = (float*)d_out;

    prep_kernel<<<(N_NODES * 32 + 1023) / 1024, 1024>>>(W, (const int*)src,
                                                        (const float4*)feat);
    hist_kernel<<<(N_EDGES + 511) / 512, 512>>>(dst);
    scan_kernel<<<(N_NODES + 1023) / 1024, 1024>>>();
    fill_kernel<<<(N_EDGES + 511) / 512, 512>>>(src, dst);
    gather_kernel<<<(N_NODES * 32) / 256, 256>>>((const float4*)feat);

    cudaFuncSetAttribute(gemm_mma,
                         cudaFuncAttributeMaxDynamicSharedMemorySize, GEMM_SMEM);
    dim3 grid((N_NODES + A_ROWS - 1) / A_ROWS, 2);
    gemm_mma<<<grid, 256, GEMM_SMEM>>>(out);
}